// round 5
// baseline (speedup 1.0000x reference)
#include <cuda_runtime.h>
#include <cstdint>
#include <math.h>

#define BB 4
#define SS 2048
#define DD 768
#define HH 12
#define DKK 64
#define PAD 72

typedef unsigned long long ull;

static const long long OUT_ELEMS  = (long long)BB * SS * DD;
static const long long ATTN_ELEMS = (long long)BB * HH * SS * SS;

// Scratch
__device__ float g_q[BB * HH * SS * DKK];
__device__ float g_k[BB * HH * SS * DKK];
__device__ float g_v[BB * HH * SS * DKK];
__device__ float g_ctx[BB * SS * DD];
__device__ float g_pre[BB * SS * DD];
__device__ float g_psum[(size_t)BB * HH * SS * 32];
__device__ float g_rowinv[(size_t)BB * HH * SS];
__device__ uint32_t g_maskbits[(size_t)BB * SS * (SS / 32)];  // 2 MB
__device__ float g_attn_fb[(long long)BB * HH * SS * SS];

// D = A(16x8,row) * B(8x8,col) + D, tf32 in (raw fp32 bits, HW-truncated), fp32 accum
__device__ __forceinline__ void mma8(float* c, const uint32_t* a, const uint32_t* b) {
    asm("mma.sync.aligned.m16n8k8.row.col.f32.tf32.tf32.f32 "
        "{%0,%1,%2,%3},{%4,%5,%6,%7},{%8,%9},{%0,%1,%2,%3};"
        : "+f"(c[0]), "+f"(c[1]), "+f"(c[2]), "+f"(c[3])
        : "r"(a[0]), "r"(a[1]), "r"(a[2]), "r"(a[3]), "r"(b[0]), "r"(b[1]));
}

// phys position of logical k within its octet: pairs (t, t+4) -> (2t, 2t+1)
__device__ __forceinline__ int kbase4(int c) {   // for float4-aligned logical c
    return (c & ~7) | ((c >> 2) & 1);            // store v[i] at +2*i
}
__device__ __forceinline__ int kphys(int k) {
    return (k & ~7) + ((k & 3) * 2) + ((k >> 2) & 1);
}

// ---------------------------------------------------------------------------
// Mask bit-pack: 4x2048x2048 int32 -> 4x2048x64 u32 bitmask. bit=1 -> masked.
// ---------------------------------------------------------------------------
__global__ void __launch_bounds__(256) maskpack_kernel(const int* __restrict__ pad)
{
    size_t w = (size_t)blockIdx.x * 256 + threadIdx.x;    // 524288 words
    const int4* p = reinterpret_cast<const int4*>(pad + w * 32);
    uint32_t bits = 0;
    #pragma unroll
    for (int t = 0; t < 8; t++) {
        int4 v = p[t];
        bits |= (uint32_t)(v.x != 0) << (4 * t);
        bits |= (uint32_t)(v.y != 0) << (4 * t + 1);
        bits |= (uint32_t)(v.z != 0) << (4 * t + 2);
        bits |= (uint32_t)(v.w != 0) << (4 * t + 3);
    }
    g_maskbits[w] = bits;
}

// ---------------------------------------------------------------------------
// Projection / output GEMM via tf32 MMA. Y[8192,768] = X @ W + bias (+resid).
// Block tile 128x64, warp 32x32, k-chunk 64. W staged transposed+permuted.
// ---------------------------------------------------------------------------
template <int MODE>
__global__ void __launch_bounds__(256) proj_kernel(
    const float* __restrict__ Xext, const float* __restrict__ W,
    const float* __restrict__ bias, const float* __restrict__ resid)
{
    const float* X = (MODE == 3) ? g_ctx : Xext;
    float* Y = (MODE == 0) ? g_q : (MODE == 1) ? g_k : (MODE == 2) ? g_v : g_pre;

    extern __shared__ uint32_t sm[];
    uint32_t (*Xs)[PAD]  = reinterpret_cast<uint32_t(*)[PAD]>(sm);             // [128][72]
    uint32_t (*Wst)[PAD] = reinterpret_cast<uint32_t(*)[PAD]>(sm + 128 * PAD); // [64][72] (n-major)

    const int tid = threadIdx.x, wid = tid >> 5, lane = tid & 31;
    const int gid = lane >> 2, tig = lane & 3;
    const int m0 = blockIdx.y * 128, n0 = blockIdx.x * 64;
    const int wm = (wid >> 1) * 32, wn = (wid & 1) * 32;

    float acc[2][4][4] = {};

    for (int k0 = 0; k0 < DD; k0 += 64) {
        #pragma unroll
        for (int t = 0; t < 8; t++) {
            int e = (tid + t * 256) * 4, r = e >> 6, c = e & 63;
            float4 v = *reinterpret_cast<const float4*>(X + (size_t)(m0 + r) * DD + k0 + c);
            int b = kbase4(c);
            Xs[r][b]     = __float_as_uint(v.x);
            Xs[r][b + 2] = __float_as_uint(v.y);
            Xs[r][b + 4] = __float_as_uint(v.z);
            Xs[r][b + 6] = __float_as_uint(v.w);
        }
        #pragma unroll
        for (int t = 0; t < 4; t++) {
            int e = (tid + t * 256) * 4, r = e >> 6, c = e & 63;  // r=k, c=n
            float4 v = *reinterpret_cast<const float4*>(W + (size_t)(k0 + r) * DD + n0 + c);
            int p = kphys(r);
            Wst[c][p]     = __float_as_uint(v.x);
            Wst[c + 1][p] = __float_as_uint(v.y);
            Wst[c + 2][p] = __float_as_uint(v.z);
            Wst[c + 3][p] = __float_as_uint(v.w);
        }
        __syncthreads();
        #pragma unroll
        for (int kk = 0; kk < 64; kk += 8) {
            uint32_t a[2][4], b[4][2];
            #pragma unroll
            for (int mi = 0; mi < 2; mi++) {
                int r = wm + mi * 16 + gid;
                uint2 lo = *reinterpret_cast<const uint2*>(&Xs[r][kk + tig * 2]);
                uint2 hi = *reinterpret_cast<const uint2*>(&Xs[r + 8][kk + tig * 2]);
                a[mi][0] = lo.x; a[mi][1] = hi.x; a[mi][2] = lo.y; a[mi][3] = hi.y;
            }
            #pragma unroll
            for (int nj = 0; nj < 4; nj++) {
                int n = wn + nj * 8 + gid;
                uint2 bb = *reinterpret_cast<const uint2*>(&Wst[n][kk + tig * 2]);
                b[nj][0] = bb.x; b[nj][1] = bb.y;
            }
            #pragma unroll
            for (int mi = 0; mi < 2; mi++)
                #pragma unroll
                for (int nj = 0; nj < 4; nj++) mma8(acc[mi][nj], a[mi], b[nj]);
        }
        __syncthreads();
    }

    #pragma unroll
    for (int mi = 0; mi < 2; mi++)
        #pragma unroll
        for (int rr = 0; rr < 2; rr++) {
            int r = m0 + wm + mi * 16 + gid + rr * 8;
            #pragma unroll
            for (int nj = 0; nj < 4; nj++) {
                int c = n0 + wn + nj * 8 + tig * 2;
                float v0 = acc[mi][nj][rr * 2 + 0] + bias[c];
                float v1 = acc[mi][nj][rr * 2 + 1] + bias[c + 1];
                if (MODE <= 2) {
                    int b_ = r / SS, s = r % SS, h = c / DKK, d = c % DKK;
                    *reinterpret_cast<float2*>(&Y[(((size_t)b_ * HH + h) * SS + s) * DKK + d]) =
                        make_float2(v0, v1);
                } else {
                    const float2 rs = *reinterpret_cast<const float2*>(&resid[(size_t)r * DD + c]);
                    *reinterpret_cast<float2*>(&Y[(size_t)r * DD + c]) =
                        make_float2(v0 + rs.x, v1 + rs.y);
                }
            }
        }
}

// ---------------------------------------------------------------------------
// Scores+exp: 128x128 tile of exp((q.k)/8) (0 if masked) + per-tile row sums.
// ---------------------------------------------------------------------------
__global__ void __launch_bounds__(256) scores_kernel(float* __restrict__ attn_ext)
{
    float* attn = attn_ext ? attn_ext : g_attn_fb;
    extern __shared__ uint32_t sm[];
    uint32_t (*Qs)[PAD] = reinterpret_cast<uint32_t(*)[PAD]>(sm);             // [128][72]
    uint32_t (*Ks)[PAD] = reinterpret_cast<uint32_t(*)[PAD]>(sm + 128 * PAD); // [128][72]

    const int bh = blockIdx.z, b_ = bh / HH;
    const int q0 = blockIdx.y * 128, k0 = blockIdx.x * 128;
    const int tid = threadIdx.x, wid = tid >> 5, lane = tid & 31;
    const int gid = lane >> 2, tig = lane & 3;
    const int wm = (wid >> 1) * 32, wn = (wid & 1) * 64;

    const float* qp = g_q + ((size_t)bh * SS + q0) * DKK;
    const float* kp = g_k + ((size_t)bh * SS + k0) * DKK;

    #pragma unroll
    for (int t = 0; t < 8; t++) {
        int e = (tid + t * 256) * 4, r = e >> 6, c = e & 63;
        int b = kbase4(c);
        float4 v = *reinterpret_cast<const float4*>(qp + (size_t)r * DKK + c);
        Qs[r][b] = __float_as_uint(v.x); Qs[r][b+2] = __float_as_uint(v.y);
        Qs[r][b+4] = __float_as_uint(v.z); Qs[r][b+6] = __float_as_uint(v.w);
        float4 w = *reinterpret_cast<const float4*>(kp + (size_t)r * DKK + c);
        Ks[r][b] = __float_as_uint(w.x); Ks[r][b+2] = __float_as_uint(w.y);
        Ks[r][b+4] = __float_as_uint(w.z); Ks[r][b+6] = __float_as_uint(w.w);
    }
    __syncthreads();

    float acc[2][8][4] = {};
    #pragma unroll
    for (int kk = 0; kk < 64; kk += 8) {
        uint32_t a[2][4], b[8][2];
        #pragma unroll
        for (int mi = 0; mi < 2; mi++) {
            int r = wm + mi * 16 + gid;
            uint2 lo = *reinterpret_cast<const uint2*>(&Qs[r][kk + tig * 2]);
            uint2 hi = *reinterpret_cast<const uint2*>(&Qs[r + 8][kk + tig * 2]);
            a[mi][0] = lo.x; a[mi][1] = hi.x; a[mi][2] = lo.y; a[mi][3] = hi.y;
        }
        #pragma unroll
        for (int nj = 0; nj < 8; nj++) {
            int n = wn + nj * 8 + gid;
            uint2 bb = *reinterpret_cast<const uint2*>(&Ks[n][kk + tig * 2]);
            b[nj][0] = bb.x; b[nj][1] = bb.y;
        }
        #pragma unroll
        for (int mi = 0; mi < 2; mi++)
            #pragma unroll
            for (int nj = 0; nj < 8; nj++) mma8(acc[mi][nj], a[mi], b[nj]);
    }

    const size_t base = (size_t)bh * SS * SS;
    #pragma unroll
    for (int mi = 0; mi < 2; mi++)
        #pragma unroll
        for (int rr = 0; rr < 2; rr++) {
            int qr = q0 + wm + mi * 16 + gid + rr * 8;
            uint2 mw = *reinterpret_cast<const uint2*>(
                g_maskbits + ((size_t)b_ * SS + qr) * (SS / 32) + (k0 + wn) / 32);
            ull m64 = (ull)mw.x | ((ull)mw.y << 32);
            float rs = 0.f;
            #pragma unroll
            for (int nj = 0; nj < 8; nj++) {
                int j = nj * 8 + tig * 2;
                float v0 = acc[mi][nj][rr * 2 + 0] * 0.125f;
                float v1 = acc[mi][nj][rr * 2 + 1] * 0.125f;
                float p0 = ((m64 >> j) & 1ull) ? 0.f : __expf(v0);
                float p1 = ((m64 >> (j + 1)) & 1ull) ? 0.f : __expf(v1);
                rs += p0 + p1;
                *reinterpret_cast<float2*>(attn + base + (size_t)qr * SS + k0 + wn + j) =
                    make_float2(p0, p1);
            }
            rs += __shfl_xor_sync(~0u, rs, 1);
            rs += __shfl_xor_sync(~0u, rs, 2);
            if (tig == 0)
                g_psum[((size_t)bh * SS + qr) * 32 + blockIdx.x * 2 + (wid & 1)] = rs;
        }
}

// ---------------------------------------------------------------------------
// Row-sum reduce -> 1/sum.
// ---------------------------------------------------------------------------
__global__ void __launch_bounds__(256) rowinv_kernel()
{
    size_t idx = (size_t)blockIdx.x * 256 + threadIdx.x;
    const float4* p = reinterpret_cast<const float4*>(g_psum + idx * 32);
    float s = 0.f;
    #pragma unroll
    for (int t = 0; t < 8; t++) { float4 v = p[t]; s += v.x + v.y + v.z + v.w; }
    g_rowinv[idx] = 1.0f / s;
}

// ---------------------------------------------------------------------------
// Context: normalize exp on load (write final attn), MMA with V.
// ---------------------------------------------------------------------------
__global__ void __launch_bounds__(256) context_kernel(float* __restrict__ attn_ext)
{
    float* attn = attn_ext ? attn_ext : g_attn_fb;
    extern __shared__ uint32_t sm[];
    uint32_t (*Ast)[PAD] = reinterpret_cast<uint32_t(*)[PAD]>(sm);             // [128][72]
    uint32_t (*Vst)[PAD] = reinterpret_cast<uint32_t(*)[PAD]>(sm + 128 * PAD); // [64][72] (dv-major)

    const int bh = blockIdx.y, q0 = blockIdx.x * 128;
    const int tid = threadIdx.x, wid = tid >> 5, lane = tid & 31;
    const int gid = lane >> 2, tig = lane & 3;
    const int wm = (wid >> 1) * 32, wn = (wid & 1) * 32;

    float* ap = attn + ((size_t)bh * SS + q0) * SS;
    const float* vp = g_v + (size_t)bh * SS * DKK;
    const float* invp = g_rowinv + (size_t)bh * SS + q0;

    float acc[2][4][4] = {};

    for (int k0 = 0; k0 < SS; k0 += 64) {
        #pragma unroll
        for (int t = 0; t < 8; t++) {
            int e = (tid + t * 256) * 4, r = e >> 6, c = e & 63;
            float inv = invp[r];
            float* gp = ap + (size_t)r * SS + k0 + c;
            float4 v = *reinterpret_cast<const float4*>(gp);
            v.x *= inv; v.y *= inv; v.z *= inv; v.w *= inv;
            *reinterpret_cast<float4*>(gp) = v;    // final normalized attn
            int b = kbase4(c);
            Ast[r][b] = __float_as_uint(v.x); Ast[r][b+2] = __float_as_uint(v.y);
            Ast[r][b+4] = __float_as_uint(v.z); Ast[r][b+6] = __float_as_uint(v.w);
        }
        #pragma unroll
        for (int t = 0; t < 4; t++) {
            int e = (tid + t * 256) * 4, r = e >> 6, c = e & 63;   // r=k, c=dv
            float4 v = *reinterpret_cast<const float4*>(vp + (size_t)(k0 + r) * DKK + c);
            int p = kphys(r);
            Vst[c][p]     = __float_as_uint(v.x);
            Vst[c + 1][p] = __float_as_uint(v.y);
            Vst[c + 2][p] = __float_as_uint(v.z);
            Vst[c + 3][p] = __float_as_uint(v.w);
        }
        __syncthreads();
        #pragma unroll
        for (int kk = 0; kk < 64; kk += 8) {
            uint32_t a[2][4], b[4][2];
            #pragma unroll
            for (int mi = 0; mi < 2; mi++) {
                int r = wm + mi * 16 + gid;
                uint2 lo = *reinterpret_cast<const uint2*>(&Ast[r][kk + tig * 2]);
                uint2 hi = *reinterpret_cast<const uint2*>(&Ast[r + 8][kk + tig * 2]);
                a[mi][0] = lo.x; a[mi][1] = hi.x; a[mi][2] = lo.y; a[mi][3] = hi.y;
            }
            #pragma unroll
            for (int nj = 0; nj < 4; nj++) {
                int n = wn + nj * 8 + gid;
                uint2 bb = *reinterpret_cast<const uint2*>(&Vst[n][kk + tig * 2]);
                b[nj][0] = bb.x; b[nj][1] = bb.y;
            }
            #pragma unroll
            for (int mi = 0; mi < 2; mi++)
                #pragma unroll
                for (int nj = 0; nj < 4; nj++) mma8(acc[mi][nj], a[mi], b[nj]);
        }
        __syncthreads();
    }

    const int b_ = bh / HH, h = bh % HH;
    #pragma unroll
    for (int mi = 0; mi < 2; mi++)
        #pragma unroll
        for (int rr = 0; rr < 2; rr++) {
            int s = q0 + wm + mi * 16 + gid + rr * 8;
            #pragma unroll
            for (int nj = 0; nj < 4; nj++) {
                int d = wn + nj * 8 + tig * 2;
                *reinterpret_cast<float2*>(&g_ctx[((size_t)b_ * SS + s) * DD + h * DKK + d]) =
                    make_float2(acc[mi][nj][rr * 2], acc[mi][nj][rr * 2 + 1]);
            }
        }
}

// ---------------------------------------------------------------------------
// LayerNorm over D=768.
// ---------------------------------------------------------------------------
__global__ void __launch_bounds__(256) ln_kernel(
    const float* __restrict__ lg, const float* __restrict__ lb, float* __restrict__ out)
{
    const size_t row = blockIdx.x;
    const float* x = g_pre + row * DD;
    const int tid = threadIdx.x;
    __shared__ float red[8];

    float v[3];
    float s = 0.f;
    #pragma unroll
    for (int t = 0; t < 3; t++) { v[t] = x[tid + t * 256]; s += v[t]; }
    #pragma unroll
    for (int o = 16; o; o >>= 1) s += __shfl_xor_sync(~0u, s, o);
    if ((tid & 31) == 0) red[tid >> 5] = s;
    __syncthreads();
    s = 0.f;
    #pragma unroll
    for (int w = 0; w < 8; w++) s += red[w];
    const float mu = s * (1.0f / DD);
    __syncthreads();

    float var = 0.f;
    #pragma unroll
    for (int t = 0; t < 3; t++) { float d = v[t] - mu; var += d * d; }
    #pragma unroll
    for (int o = 16; o; o >>= 1) var += __shfl_xor_sync(~0u, var, o);
    if ((tid & 31) == 0) red[tid >> 5] = var;
    __syncthreads();
    var = 0.f;
    #pragma unroll
    for (int w = 0; w < 8; w++) var += red[w];
    const float inv = rsqrtf(var * (1.0f / DD) + 1e-5f);

    #pragma unroll
    for (int t = 0; t < 3; t++) {
        int c = tid + t * 256;
        out[row * DD + c] = (v[t] - mu) * inv * lg[c] + lb[c];
    }
}

// ---------------------------------------------------------------------------
extern "C" void kernel_launch(void* const* d_in, const int* in_sizes, int n_in,
                              void* d_out, int out_size)
{
    const float* Q  = (const float*)d_in[0];
    const float* K  = (const float*)d_in[1];
    const float* V  = (const float*)d_in[2];
    const int*   pad = (const int*)d_in[3];
    const float* Wq = (const float*)d_in[4];
    const float* bq = (const float*)d_in[5];
    const float* Wk = (const float*)d_in[6];
    const float* bk = (const float*)d_in[7];
    const float* Wv = (const float*)d_in[8];
    const float* bv = (const float*)d_in[9];
    const float* Wo = (const float*)d_in[10];
    const float* bo = (const float*)d_in[11];
    const float* lg = (const float*)d_in[12];
    const float* lb = (const float*)d_in[13];
    float* out = (float*)d_out;

    float* attn = ((long long)out_size >= OUT_ELEMS + ATTN_ELEMS) ? (out + OUT_ELEMS)
                                                                  : nullptr;

    const int PROJ_SMEM   = (128 + 64) * PAD * 4;   // 55296
    const int SCORES_SMEM = 256 * PAD * 4;          // 73728
    const int CTX_SMEM    = (128 + 64) * PAD * 4;   // 55296
    cudaFuncSetAttribute(proj_kernel<0>, cudaFuncAttributeMaxDynamicSharedMemorySize, PROJ_SMEM);
    cudaFuncSetAttribute(proj_kernel<1>, cudaFuncAttributeMaxDynamicSharedMemorySize, PROJ_SMEM);
    cudaFuncSetAttribute(proj_kernel<2>, cudaFuncAttributeMaxDynamicSharedMemorySize, PROJ_SMEM);
    cudaFuncSetAttribute(proj_kernel<3>, cudaFuncAttributeMaxDynamicSharedMemorySize, PROJ_SMEM);
    cudaFuncSetAttribute(scores_kernel, cudaFuncAttributeMaxDynamicSharedMemorySize, SCORES_SMEM);
    cudaFuncSetAttribute(context_kernel, cudaFuncAttributeMaxDynamicSharedMemorySize, CTX_SMEM);

    maskpack_kernel<<<(BB * SS * (SS / 32)) / 256, 256>>>(pad);

    dim3 gp(DD / 64, (BB * SS) / 128);          // (12, 64)
    proj_kernel<0><<<gp, 256, PROJ_SMEM>>>(Q, Wq, bq, nullptr);
    proj_kernel<1><<<gp, 256, PROJ_SMEM>>>(K, Wk, bk, nullptr);
    proj_kernel<2><<<gp, 256, PROJ_SMEM>>>(V, Wv, bv, nullptr);

    dim3 gs(SS / 128, SS / 128, BB * HH);       // (16, 16, 48)
    scores_kernel<<<gs, 256, SCORES_SMEM>>>(attn);

    rowinv_kernel<<<(BB * HH * SS) / 256, 256>>>();

    dim3 gc(SS / 128, BB * HH);                 // (16, 48)
    context_kernel<<<gc, 256, CTX_SMEM>>>(attn);

    proj_kernel<3><<<gp, 256, PROJ_SMEM>>>(nullptr, Wo, bo, Q);

    ln_kernel<<<BB * SS, 256>>>(lg, lb, out);
}

// round 6
// speedup vs baseline: 1.7722x; 1.7722x over previous
#include <cuda_runtime.h>
#include <cstdint>
#include <math.h>

#define BB 4
#define SS 2048
#define DD 768
#define HH 12
#define DKK 64

typedef unsigned long long ull;

static const long long OUT_ELEMS  = (long long)BB * SS * DD;
static const long long ATTN_ELEMS = (long long)BB * HH * SS * SS;

// Scratch
__device__ float g_q[BB * HH * SS * DKK];
__device__ float g_k[BB * HH * SS * DKK];
__device__ float g_v[BB * HH * SS * DKK];
__device__ float g_ctx[BB * SS * DD];
__device__ float g_pre[BB * SS * DD];
__device__ float g_psum[(size_t)BB * HH * SS * 32];
__device__ float g_rowinv[(size_t)BB * HH * SS];
__device__ uint32_t g_maskbits[(size_t)BB * SS * (SS / 32)];  // 2 MB
__device__ float g_attn_fb[(long long)BB * HH * SS * SS];

__device__ __forceinline__ uint32_t cvt_tf32(float x) {
    uint32_t u; asm("cvt.rna.tf32.f32 %0, %1;" : "=r"(u) : "f"(x)); return u;
}

__device__ __forceinline__ void mma8(float* c, const uint32_t* a, const uint32_t* b) {
    asm("mma.sync.aligned.m16n8k8.row.col.f32.tf32.tf32.f32 "
        "{%0,%1,%2,%3},{%4,%5,%6,%7},{%8,%9},{%0,%1,%2,%3};"
        : "+f"(c[0]), "+f"(c[1]), "+f"(c[2]), "+f"(c[3])
        : "r"(a[0]), "r"(a[1]), "r"(a[2]), "r"(a[3]), "r"(b[0]), "r"(b[1]));
}

__device__ __forceinline__ void cp16(uint32_t dst, const void* src) {
    asm volatile("cp.async.cg.shared.global [%0], [%1], 16;" :: "r"(dst), "l"(src));
}
__device__ __forceinline__ void cp_commit() { asm volatile("cp.async.commit_group;"); }
template<int N> __device__ __forceinline__ void cp_wait() {
    asm volatile("cp.async.wait_group %0;" :: "n"(N));
}

// ---------------------------------------------------------------------------
// Mask bit-pack: int32 [4,2048,2048] -> bitmask. bit=1 -> masked.
// ---------------------------------------------------------------------------
__global__ void __launch_bounds__(256) maskpack_kernel(const int* __restrict__ pad)
{
    size_t w = (size_t)blockIdx.x * 256 + threadIdx.x;
    const int4* p = reinterpret_cast<const int4*>(pad + w * 32);
    uint32_t bits = 0;
    #pragma unroll
    for (int t = 0; t < 8; t++) {
        int4 v = p[t];
        bits |= (uint32_t)(v.x != 0) << (4 * t);
        bits |= (uint32_t)(v.y != 0) << (4 * t + 1);
        bits |= (uint32_t)(v.z != 0) << (4 * t + 2);
        bits |= (uint32_t)(v.w != 0) << (4 * t + 3);
    }
    g_maskbits[w] = bits;
}

// ---------------------------------------------------------------------------
// QKV projection (merged, grid.z selects Q/K/V): Y = X @ W + bias,
// written in [B,H,S,DK] layout. cp.async double-buffered, tf32 MMA.
// Block tile 128x64, warps 2x2 of 32x32.
// smem floats: Xs stage s at s*8704 [128][68]; Ws at 17408+s*4352 [64][68].
// ---------------------------------------------------------------------------
__global__ void __launch_bounds__(256) qkv_kernel(
    const float* __restrict__ Q, const float* __restrict__ K, const float* __restrict__ V,
    const float* __restrict__ Wq, const float* __restrict__ Wk, const float* __restrict__ Wv,
    const float* __restrict__ bq, const float* __restrict__ bk, const float* __restrict__ bv)
{
    const int z = blockIdx.z;
    const float* X = (z == 0) ? Q : (z == 1) ? K : V;
    const float* W = (z == 0) ? Wq : (z == 1) ? Wk : Wv;
    const float* bias = (z == 0) ? bq : (z == 1) ? bk : bv;
    float* Y = (z == 0) ? g_q : (z == 1) ? g_k : g_v;

    extern __shared__ float smf[];
    const uint32_t smb = (uint32_t)__cvta_generic_to_shared(smf);

    const int tid = threadIdx.x, wid = tid >> 5, lane = tid & 31;
    const int gid = lane >> 2, tig = lane & 3;
    const int m0 = blockIdx.y * 128, n0 = blockIdx.x * 64;
    const int wm = (wid >> 1) * 32, wn = (wid & 1) * 32;

    float acc[2][4][4] = {};

    #define XS(s,r,c) smf[(s)*8704 + (r)*68 + (c)]
    #define WS(s,r,c) smf[17408 + (s)*4352 + (r)*68 + (c)]

    auto load_chunk = [&](int s, int k0) {
        #pragma unroll
        for (int t = 0; t < 8; t++) {
            int e = (tid + t * 256) * 4, r = e >> 6, c = e & 63;
            cp16(smb + (uint32_t)((s * 8704 + r * 68 + c) * 4),
                 X + (size_t)(m0 + r) * DD + k0 + c);
        }
        #pragma unroll
        for (int t = 0; t < 4; t++) {
            int e = (tid + t * 256) * 4, r = e >> 6, c = e & 63;
            cp16(smb + (uint32_t)((17408 + s * 4352 + r * 68 + c) * 4),
                 W + (size_t)(k0 + r) * DD + n0 + c);
        }
        cp_commit();
    };

    load_chunk(0, 0);
    for (int it = 0; it < 12; it++) {
        if (it + 1 < 12) { load_chunk((it + 1) & 1, (it + 1) * 64); cp_wait<1>(); }
        else cp_wait<0>();
        __syncthreads();
        const int s = it & 1;
        #pragma unroll
        for (int kk = 0; kk < 64; kk += 8) {
            uint32_t a[2][4], b[4][2];
            #pragma unroll
            for (int mi = 0; mi < 2; mi++) {
                int r = wm + mi * 16 + gid;
                a[mi][0] = cvt_tf32(XS(s, r, kk + tig));
                a[mi][1] = cvt_tf32(XS(s, r + 8, kk + tig));
                a[mi][2] = cvt_tf32(XS(s, r, kk + tig + 4));
                a[mi][3] = cvt_tf32(XS(s, r + 8, kk + tig + 4));
            }
            #pragma unroll
            for (int nj = 0; nj < 4; nj++) {
                int n = wn + nj * 8 + gid;
                b[nj][0] = cvt_tf32(WS(s, kk + tig, n));
                b[nj][1] = cvt_tf32(WS(s, kk + tig + 4, n));
            }
            #pragma unroll
            for (int mi = 0; mi < 2; mi++)
                #pragma unroll
                for (int nj = 0; nj < 4; nj++) mma8(acc[mi][nj], a[mi], b[nj]);
        }
        __syncthreads();
    }
    #undef XS
    #undef WS

    #pragma unroll
    for (int mi = 0; mi < 2; mi++)
        #pragma unroll
        for (int rr = 0; rr < 2; rr++) {
            int r = m0 + wm + mi * 16 + gid + rr * 8;
            #pragma unroll
            for (int nj = 0; nj < 4; nj++) {
                int c = n0 + wn + nj * 8 + tig * 2;
                float v0 = acc[mi][nj][rr * 2 + 0] + bias[c];
                float v1 = acc[mi][nj][rr * 2 + 1] + bias[c + 1];
                int b_ = r / SS, sidx = r % SS, h = c / DKK, d = c % DKK;
                *reinterpret_cast<float2*>(&Y[(((size_t)b_ * HH + h) * SS + sidx) * DKK + d]) =
                    make_float2(v0, v1);
            }
        }
}

// ---------------------------------------------------------------------------
// Output projection: g_pre = g_ctx @ Wo + bo + resid. Same pipeline.
// ---------------------------------------------------------------------------
__global__ void __launch_bounds__(256) outproj_kernel(
    const float* __restrict__ W, const float* __restrict__ bias,
    const float* __restrict__ resid)
{
    const float* X = g_ctx;
    extern __shared__ float smf[];
    const uint32_t smb = (uint32_t)__cvta_generic_to_shared(smf);

    const int tid = threadIdx.x, wid = tid >> 5, lane = tid & 31;
    const int gid = lane >> 2, tig = lane & 3;
    const int m0 = blockIdx.y * 128, n0 = blockIdx.x * 64;
    const int wm = (wid >> 1) * 32, wn = (wid & 1) * 32;

    float acc[2][4][4] = {};

    #define XS(s,r,c) smf[(s)*8704 + (r)*68 + (c)]
    #define WS(s,r,c) smf[17408 + (s)*4352 + (r)*68 + (c)]
    auto load_chunk = [&](int s, int k0) {
        #pragma unroll
        for (int t = 0; t < 8; t++) {
            int e = (tid + t * 256) * 4, r = e >> 6, c = e & 63;
            cp16(smb + (uint32_t)((s * 8704 + r * 68 + c) * 4),
                 X + (size_t)(m0 + r) * DD + k0 + c);
        }
        #pragma unroll
        for (int t = 0; t < 4; t++) {
            int e = (tid + t * 256) * 4, r = e >> 6, c = e & 63;
            cp16(smb + (uint32_t)((17408 + s * 4352 + r * 68 + c) * 4),
                 W + (size_t)(k0 + r) * DD + n0 + c);
        }
        cp_commit();
    };

    load_chunk(0, 0);
    for (int it = 0; it < 12; it++) {
        if (it + 1 < 12) { load_chunk((it + 1) & 1, (it + 1) * 64); cp_wait<1>(); }
        else cp_wait<0>();
        __syncthreads();
        const int s = it & 1;
        #pragma unroll
        for (int kk = 0; kk < 64; kk += 8) {
            uint32_t a[2][4], b[4][2];
            #pragma unroll
            for (int mi = 0; mi < 2; mi++) {
                int r = wm + mi * 16 + gid;
                a[mi][0] = cvt_tf32(XS(s, r, kk + tig));
                a[mi][1] = cvt_tf32(XS(s, r + 8, kk + tig));
                a[mi][2] = cvt_tf32(XS(s, r, kk + tig + 4));
                a[mi][3] = cvt_tf32(XS(s, r + 8, kk + tig + 4));
            }
            #pragma unroll
            for (int nj = 0; nj < 4; nj++) {
                int n = wn + nj * 8 + gid;
                b[nj][0] = cvt_tf32(WS(s, kk + tig, n));
                b[nj][1] = cvt_tf32(WS(s, kk + tig + 4, n));
            }
            #pragma unroll
            for (int mi = 0; mi < 2; mi++)
                #pragma unroll
                for (int nj = 0; nj < 4; nj++) mma8(acc[mi][nj], a[mi], b[nj]);
        }
        __syncthreads();
    }
    #undef XS
    #undef WS

    #pragma unroll
    for (int mi = 0; mi < 2; mi++)
        #pragma unroll
        for (int rr = 0; rr < 2; rr++) {
            int r = m0 + wm + mi * 16 + gid + rr * 8;
            #pragma unroll
            for (int nj = 0; nj < 4; nj++) {
                int c = n0 + wn + nj * 8 + tig * 2;
                float v0 = acc[mi][nj][rr * 2 + 0] + bias[c];
                float v1 = acc[mi][nj][rr * 2 + 1] + bias[c + 1];
                const float2 rs = *reinterpret_cast<const float2*>(&resid[(size_t)r * DD + c]);
                *reinterpret_cast<float2*>(&g_pre[(size_t)r * DD + c]) =
                    make_float2(v0 + rs.x, v1 + rs.y);
            }
        }
}

// ---------------------------------------------------------------------------
// Scores+exp: 128x128 tile of exp((q.k)/8) (0 if masked) + per-tile row sums.
// Exp tile staged through smem -> coalesced float4 global writes.
// smem: Qs u32[128][68] @0, Ks u32[128][68] @128*68; union Ss f32[128][132] @0.
// ---------------------------------------------------------------------------
__global__ void __launch_bounds__(256) scores_kernel(float* __restrict__ attn_ext)
{
    float* attn = attn_ext ? attn_ext : g_attn_fb;
    extern __shared__ uint32_t smu[];
    uint32_t (*Qs)[68] = reinterpret_cast<uint32_t(*)[68]>(smu);
    uint32_t (*Ks)[68] = reinterpret_cast<uint32_t(*)[68]>(smu + 128 * 68);
    float (*Ss)[132]   = reinterpret_cast<float(*)[132]>(smu);

    const int bh = blockIdx.z, b_ = bh / HH;
    const int q0 = blockIdx.y * 128, k0 = blockIdx.x * 128;
    const int tid = threadIdx.x, wid = tid >> 5, lane = tid & 31;
    const int gid = lane >> 2, tig = lane & 3;
    const int wm = (wid >> 1) * 32, wn = (wid & 1) * 64;

    const float* qp = g_q + ((size_t)bh * SS + q0) * DKK;
    const float* kp = g_k + ((size_t)bh * SS + k0) * DKK;

    #pragma unroll
    for (int t = 0; t < 8; t++) {
        int e = (tid + t * 256) * 4, r = e >> 6, c = e & 63;
        float4 v = *reinterpret_cast<const float4*>(qp + (size_t)r * DKK + c);
        Qs[r][c] = cvt_tf32(v.x); Qs[r][c+1] = cvt_tf32(v.y);
        Qs[r][c+2] = cvt_tf32(v.z); Qs[r][c+3] = cvt_tf32(v.w);
        float4 w = *reinterpret_cast<const float4*>(kp + (size_t)r * DKK + c);
        Ks[r][c] = cvt_tf32(w.x); Ks[r][c+1] = cvt_tf32(w.y);
        Ks[r][c+2] = cvt_tf32(w.z); Ks[r][c+3] = cvt_tf32(w.w);
    }
    __syncthreads();

    float acc[2][8][4] = {};
    #pragma unroll
    for (int kk = 0; kk < 64; kk += 8) {
        uint32_t a[2][4], b[8][2];
        #pragma unroll
        for (int mi = 0; mi < 2; mi++) {
            int r = wm + mi * 16 + gid;
            a[mi][0] = Qs[r][kk + tig];     a[mi][1] = Qs[r + 8][kk + tig];
            a[mi][2] = Qs[r][kk + tig + 4]; a[mi][3] = Qs[r + 8][kk + tig + 4];
        }
        #pragma unroll
        for (int nj = 0; nj < 8; nj++) {
            int n = wn + nj * 8 + gid;
            b[nj][0] = Ks[n][kk + tig]; b[nj][1] = Ks[n][kk + tig + 4];
        }
        #pragma unroll
        for (int mi = 0; mi < 2; mi++)
            #pragma unroll
            for (int nj = 0; nj < 8; nj++) mma8(acc[mi][nj], a[mi], b[nj]);
    }
    __syncthreads();   // all warps done reading Qs/Ks before Ss overwrite

    // exp + mask + psum -> Ss
    #pragma unroll
    for (int mi = 0; mi < 2; mi++)
        #pragma unroll
        for (int rr = 0; rr < 2; rr++) {
            int qrl = wm + mi * 16 + gid + rr * 8;
            int qr = q0 + qrl;
            uint2 mw = *reinterpret_cast<const uint2*>(
                g_maskbits + ((size_t)b_ * SS + qr) * (SS / 32) + (k0 + wn) / 32);
            ull m64 = (ull)mw.x | ((ull)mw.y << 32);
            float rs = 0.f;
            #pragma unroll
            for (int nj = 0; nj < 8; nj++) {
                int j = nj * 8 + tig * 2;
                float v0 = acc[mi][nj][rr * 2 + 0] * 0.125f;
                float v1 = acc[mi][nj][rr * 2 + 1] * 0.125f;
                float p0 = ((m64 >> j) & 1ull) ? 0.f : __expf(v0);
                float p1 = ((m64 >> (j + 1)) & 1ull) ? 0.f : __expf(v1);
                rs += p0 + p1;
                *reinterpret_cast<float2*>(&Ss[qrl][wn + j]) = make_float2(p0, p1);
            }
            rs += __shfl_xor_sync(~0u, rs, 1);
            rs += __shfl_xor_sync(~0u, rs, 2);
            if (tig == 0)
                g_psum[((size_t)bh * SS + qr) * 32 + blockIdx.x * 2 + (wid & 1)] = rs;
        }
    __syncthreads();

    // coalesced writeback
    const size_t base = (size_t)bh * SS * SS;
    #pragma unroll
    for (int t = 0; t < 16; t++) {
        int idx = tid + t * 256;
        int r = idx >> 5, c4 = (idx & 31) * 4;
        float4 v = *reinterpret_cast<const float4*>(&Ss[r][c4]);
        *reinterpret_cast<float4*>(attn + base + (size_t)(q0 + r) * SS + k0 + c4) = v;
    }
}

// ---------------------------------------------------------------------------
// Row-sum reduce -> 1/sum.
// ---------------------------------------------------------------------------
__global__ void __launch_bounds__(256) rowinv_kernel()
{
    size_t idx = (size_t)blockIdx.x * 256 + threadIdx.x;
    const float4* p = reinterpret_cast<const float4*>(g_psum + idx * 32);
    float s = 0.f;
    #pragma unroll
    for (int t = 0; t < 8; t++) { float4 v = p[t]; s += v.x + v.y + v.z + v.w; }
    g_rowinv[idx] = 1.0f / s;
}

// ---------------------------------------------------------------------------
// Context: normalize exp on load (write final attn), MMA with V.
// cp.async double-buffered over 32 k-chunks.
// smem floats: As s*8704 [128][68]; Vs 17408+s*4352 [64][68]; invs @26112[128].
// ---------------------------------------------------------------------------
__global__ void __launch_bounds__(256) context_kernel(float* __restrict__ attn_ext)
{
    float* attn = attn_ext ? attn_ext : g_attn_fb;
    extern __shared__ float smf[];
    const uint32_t smb = (uint32_t)__cvta_generic_to_shared(smf);
    float* invs = smf + 26112;

    const int bh = blockIdx.y, q0 = blockIdx.x * 128;
    const int tid = threadIdx.x, wid = tid >> 5, lane = tid & 31;
    const int gid = lane >> 2, tig = lane & 3;
    const int wm = (wid >> 1) * 32, wn = (wid & 1) * 32;

    float* ap = attn + ((size_t)bh * SS + q0) * SS;
    const float* vp = g_v + (size_t)bh * SS * DKK;

    if (tid < 128) invs[tid] = g_rowinv[(size_t)bh * SS + q0 + tid];

    #define AS(s,r,c) smf[(s)*8704 + (r)*68 + (c)]
    #define VS(s,r,c) smf[17408 + (s)*4352 + (r)*68 + (c)]
    auto load_chunk = [&](int s, int k0) {
        #pragma unroll
        for (int t = 0; t < 8; t++) {
            int e = (tid + t * 256) * 4, r = e >> 6, c = e & 63;
            cp16(smb + (uint32_t)((s * 8704 + r * 68 + c) * 4),
                 ap + (size_t)r * SS + k0 + c);
        }
        #pragma unroll
        for (int t = 0; t < 4; t++) {
            int e = (tid + t * 256) * 4, r = e >> 6, c = e & 63;
            cp16(smb + (uint32_t)((17408 + s * 4352 + r * 68 + c) * 4),
                 vp + (size_t)(k0 + r) * DKK + c);
        }
        cp_commit();
    };

    float acc[2][4][4] = {};
    load_chunk(0, 0);
    for (int it = 0; it < 32; it++) {
        if (it + 1 < 32) { load_chunk((it + 1) & 1, (it + 1) * 64); cp_wait<1>(); }
        else cp_wait<0>();
        __syncthreads();
        const int s = it & 1;
        const int k0 = it * 64;

        // normalize + global writeback + tf32-cvt in place
        #pragma unroll
        for (int t = 0; t < 8; t++) {
            int e = (tid + t * 256) * 4, r = e >> 6, c = e & 63;
            float4 v = *reinterpret_cast<const float4*>(&AS(s, r, c));
            float inv = invs[r];
            v.x *= inv; v.y *= inv; v.z *= inv; v.w *= inv;
            *reinterpret_cast<float4*>(ap + (size_t)r * SS + k0 + c) = v;
            uint32_t* u = reinterpret_cast<uint32_t*>(&AS(s, r, c));
            u[0] = cvt_tf32(v.x); u[1] = cvt_tf32(v.y);
            u[2] = cvt_tf32(v.z); u[3] = cvt_tf32(v.w);
        }
        #pragma unroll
        for (int t = 0; t < 4; t++) {
            int e = (tid + t * 256) * 4, r = e >> 6, c = e & 63;
            float4 v = *reinterpret_cast<const float4*>(&VS(s, r, c));
            uint32_t* u = reinterpret_cast<uint32_t*>(&VS(s, r, c));
            u[0] = cvt_tf32(v.x); u[1] = cvt_tf32(v.y);
            u[2] = cvt_tf32(v.z); u[3] = cvt_tf32(v.w);
        }
        __syncthreads();

        #pragma unroll
        for (int kk = 0; kk < 64; kk += 8) {
            uint32_t a[2][4], b[4][2];
            #pragma unroll
            for (int mi = 0; mi < 2; mi++) {
                int r = wm + mi * 16 + gid;
                a[mi][0] = __float_as_uint(AS(s, r, kk + tig));
                a[mi][1] = __float_as_uint(AS(s, r + 8, kk + tig));
                a[mi][2] = __float_as_uint(AS(s, r, kk + tig + 4));
                a[mi][3] = __float_as_uint(AS(s, r + 8, kk + tig + 4));
            }
            #pragma unroll
            for (int nj = 0; nj < 4; nj++) {
                int n = wn + nj * 8 + gid;
                b[nj][0] = __float_as_uint(VS(s, kk + tig, n));
                b[nj][1] = __float_as_uint(VS(s, kk + tig + 4, n));
            }
            #pragma unroll
            for (int mi = 0; mi < 2; mi++)
                #pragma unroll
                for (int nj = 0; nj < 4; nj++) mma8(acc[mi][nj], a[mi], b[nj]);
        }
        __syncthreads();
    }
    #undef AS
    #undef VS

    const int b_ = bh / HH, h = bh % HH;
    #pragma unroll
    for (int mi = 0; mi < 2; mi++)
        #pragma unroll
        for (int rr = 0; rr < 2; rr++) {
            int s = q0 + wm + mi * 16 + gid + rr * 8;
            #pragma unroll
            for (int nj = 0; nj < 4; nj++) {
                int d = wn + nj * 8 + tig * 2;
                *reinterpret_cast<float2*>(&g_ctx[((size_t)b_ * SS + s) * DD + h * DKK + d]) =
                    make_float2(acc[mi][nj][rr * 2], acc[mi][nj][rr * 2 + 1]);
            }
        }
}

// ---------------------------------------------------------------------------
// LayerNorm over D=768.
// ---------------------------------------------------------------------------
__global__ void __launch_bounds__(256) ln_kernel(
    const float* __restrict__ lg, const float* __restrict__ lb, float* __restrict__ out)
{
    const size_t row = blockIdx.x;
    const float* x = g_pre + row * DD;
    const int tid = threadIdx.x;
    __shared__ float red[8];

    float v[3];
    float s = 0.f;
    #pragma unroll
    for (int t = 0; t < 3; t++) { v[t] = x[tid + t * 256]; s += v[t]; }
    #pragma unroll
    for (int o = 16; o; o >>= 1) s += __shfl_xor_sync(~0u, s, o);
    if ((tid & 31) == 0) red[tid >> 5] = s;
    __syncthreads();
    s = 0.f;
    #pragma unroll
    for (int w = 0; w < 8; w++) s += red[w];
    const float mu = s * (1.0f / DD);
    __syncthreads();

    float var = 0.f;
    #pragma unroll
    for (int t = 0; t < 3; t++) { float d = v[t] - mu; var += d * d; }
    #pragma unroll
    for (int o = 16; o; o >>= 1) var += __shfl_xor_sync(~0u, var, o);
    if ((tid & 31) == 0) red[tid >> 5] = var;
    __syncthreads();
    var = 0.f;
    #pragma unroll
    for (int w = 0; w < 8; w++) var += red[w];
    const float inv = rsqrtf(var * (1.0f / DD) + 1e-5f);

    #pragma unroll
    for (int t = 0; t < 3; t++) {
        int c = tid + t * 256;
        out[row * DD + c] = (v[t] - mu) * inv * lg[c] + lb[c];
    }
}

// ---------------------------------------------------------------------------
extern "C" void kernel_launch(void* const* d_in, const int* in_sizes, int n_in,
                              void* d_out, int out_size)
{
    const float* Q  = (const float*)d_in[0];
    const float* K  = (const float*)d_in[1];
    const float* V  = (const float*)d_in[2];
    const int*   pad = (const int*)d_in[3];
    const float* Wq = (const float*)d_in[4];
    const float* bq = (const float*)d_in[5];
    const float* Wk = (const float*)d_in[6];
    const float* bk = (const float*)d_in[7];
    const float* Wv = (const float*)d_in[8];
    const float* bv = (const float*)d_in[9];
    const float* Wo = (const float*)d_in[10];
    const float* bo = (const float*)d_in[11];
    const float* lg = (const float*)d_in[12];
    const float* lb = (const float*)d_in[13];
    float* out = (float*)d_out;

    float* attn = ((long long)out_size >= OUT_ELEMS + ATTN_ELEMS) ? (out + OUT_ELEMS)
                                                                  : nullptr;

    const int GEMM_SMEM   = 26112 * 4;   // 104448
    const int SCORES_SMEM = 17408 * 4;   // 69632
    const int CTX_SMEM    = 26240 * 4;   // 104960
    cudaFuncSetAttribute(qkv_kernel, cudaFuncAttributeMaxDynamicSharedMemorySize, GEMM_SMEM);
    cudaFuncSetAttribute(outproj_kernel, cudaFuncAttributeMaxDynamicSharedMemorySize, GEMM_SMEM);
    cudaFuncSetAttribute(scores_kernel, cudaFuncAttributeMaxDynamicSharedMemorySize, SCORES_SMEM);
    cudaFuncSetAttribute(context_kernel, cudaFuncAttributeMaxDynamicSharedMemorySize, CTX_SMEM);

    maskpack_kernel<<<(BB * SS * (SS / 32)) / 256, 256>>>(pad);

    dim3 gq(DD / 64, (BB * SS) / 128, 3);       // (12, 64, 3)
    qkv_kernel<<<gq, 256, GEMM_SMEM>>>(Q, K, V, Wq, Wk, Wv, bq, bk, bv);

    dim3 gs(SS / 128, SS / 128, BB * HH);       // (16, 16, 48)
    scores_kernel<<<gs, 256, SCORES_SMEM>>>(attn);

    rowinv_kernel<<<(BB * HH * SS) / 256, 256>>>();

    dim3 gc(SS / 128, BB * HH);                 // (16, 48)
    context_kernel<<<gc, 256, CTX_SMEM>>>(attn);

    dim3 gp(DD / 64, (BB * SS) / 128);          // (12, 64)
    outproj_kernel<<<gp, 256, GEMM_SMEM>>>(Wo, bo, Q);

    ln_kernel<<<BB * SS, 256>>>(lg, lb, out);
}